// round 17
// baseline (speedup 1.0000x reference)
#include <cuda_runtime.h>
#include <cuda_fp16.h>
#include <math.h>
#include <stdint.h>

// ---------------- problem constants ----------------
#define NB     8
#define CIN    192
#define HH     128
#define WW     128
#define HWP    (HH * WW)        // 16384
#define C3     576              // 3 * CIN
#define HEADS  6
#define CH     32               // channels per head
#define NH     (NB * HEADS)     // 48
#define EPS    1e-12f

#define PAD    130              // padded H/W for transposed input
#define KTOT   1728             // 9 * 192

// ---------------- scratch (device globals; allocation-free) ----------------
__device__ __align__(16) float g_S[NH * CH * CH];
__device__ __align__(16) float g_qn[NH * CH];
__device__ __align__(16) float g_kn[NH * CH];
// conv output fp16 (q,k only; v goes straight to g_vt): [n][co 576][px 16384]
__device__ __align__(16) __half g_c16[NB * C3 * HWP];
// transposed + padded fp16 input: [n][prow 130][pcol 130][ci 192]
__device__ __align__(16) __half g_xt[NB * PAD * PAD * CIN];
// repacked weights fp16: [co][tap 9][ci 192]
__device__ __align__(16) __half g_wt[C3 * KTOT];
// fused attn+proj matrix, fp16: [n][co 192][d 192]
__device__ __align__(16) __half g_mh[NB * CIN * CIN];
// v transposed fp16: [n][px 16384][d 192]
__device__ __align__(16) __half g_vt[NB * HWP * CIN];

// ---------------- helpers ----------------
__device__ __forceinline__ uint32_t smem_to_u32(const void* smem_ptr) {
    uint32_t addr;
    asm("{ .reg .u64 tmp; cvta.to.shared.u64 tmp, %1; cvt.u32.u64 %0, tmp; }"
        : "=r"(addr) : "l"(smem_ptr));
    return addr;
}

#define SW128(off) ((off) ^ (((off) >> 3) & 0x70))

__device__ __forceinline__ void cpa16(uint32_t dst, const void* src) {
    asm volatile("cp.async.cg.shared.global [%0], [%1], 16;"
                 :: "r"(dst), "l"(src) : "memory");
}
#define CP_COMMIT() asm volatile("cp.async.commit_group;" ::: "memory")
#define CP_WAIT_2() asm volatile("cp.async.wait_group 2;" ::: "memory")
#define CP_WAIT_1() asm volatile("cp.async.wait_group 1;" ::: "memory")
#define CP_WAIT_0() asm volatile("cp.async.wait_group 0;" ::: "memory")

#define LDSM_X4(r, addr) \
    asm volatile("ldmatrix.sync.aligned.m8n8.x4.shared.b16 {%0,%1,%2,%3}, [%4];" \
        : "=r"((r)[0]), "=r"((r)[1]), "=r"((r)[2]), "=r"((r)[3]) : "r"(addr))

#define MMAF16(c, a, b0, b1) \
    asm volatile("mma.sync.aligned.m16n8k16.row.col.f32.f16.f16.f32 " \
        "{%0,%1,%2,%3},{%4,%5,%6,%7},{%8,%9},{%0,%1,%2,%3};" \
        : "+f"((c)[0]), "+f"((c)[1]), "+f"((c)[2]), "+f"((c)[3]) \
        : "r"((a)[0]), "r"((a)[1]), "r"((a)[2]), "r"((a)[3]), \
          "r"(b0), "r"(b1))

// ---------------- K0T: fused setup (borders + accum zero + weight repack) AND x transpose ----------------
#define BORD_PIX 516                        // 2*130 + 2*128
#define BORD_TOT (NB * BORD_PIX * CIN)      // 792576
#define KW_TOT   (C3 * KTOT)                // 995328
#define KT_BLOCKS (HH * (CIN / 32) * NB)    // 6144
#define SETUP_BLOCKS ((KW_TOT + 255) / 256) // 3888

__global__ __launch_bounds__(256) void k0t_setup_transpose(
    const float* __restrict__ wq, const float* __restrict__ x)
{
    const int bid = blockIdx.x;
    const int tid = threadIdx.x;

    if (bid >= KT_BLOCKS) {
        int i = (bid - KT_BLOCKS) * 256 + tid;
        if (i < NH * CH * CH) g_S[i] = 0.f;
        if (i < NH * CH) { g_qn[i] = 0.f; g_kn[i] = 0.f; }
        if (i < BORD_TOT) {
            int n = i / (BORD_PIX * CIN);
            int r = i % (BORD_PIX * CIN);
            int pix = r / CIN;
            int ci  = r % CIN;
            int pr, pc;
            if (pix < 130)      { pr = 0;   pc = pix; }
            else if (pix < 260) { pr = 129; pc = pix - 130; }
            else if (pix < 388) { pr = pix - 260 + 1; pc = 0; }
            else                { pr = pix - 388 + 1; pc = 129; }
            size_t idx = (((size_t)n * PAD + pr) * PAD + pc) * CIN + ci;
            g_xt[idx] = __float2half(0.f);
        }
        if (i < KW_TOT) {
            int co = i / KTOT;
            int r  = i % KTOT;
            int tap = r / CIN;
            int ci  = r % CIN;
            g_wt[i] = __float2half(wq[(size_t)co * KTOT + ci * 9 + tap]);
        }
        return;
    }

    const int r   = bid & 127;
    const int cig = (bid >> 7) % 6;
    const int n   = bid / (128 * 6);
    const int ci0 = cig * 32;

    __shared__ float t_tile[32][132];

#pragma unroll
    for (int ii = 0; ii < 16; ii++) {
        int lin = tid + ii * 256;
        int cl = lin >> 7, c = lin & 127;
        t_tile[cl][c] = x[(((size_t)n * CIN + ci0 + cl) * HH + r) * WW + c];
    }
    __syncthreads();

    const int p    = tid >> 1;
    const int half = tid & 1;

    uint32_t hb[8];
#pragma unroll
    for (int j = 0; j < 8; j++) {
        __half2 hv;
        hv.x = __float2half(t_tile[half * 16 + j * 2 + 0][p]);
        hv.y = __float2half(t_tile[half * 16 + j * 2 + 1][p]);
        hb[j] = *(uint32_t*)&hv;
    }
    size_t dst = (((size_t)n * PAD + (r + 1)) * PAD + (p + 1)) * CIN + ci0 + half * 16;
    ((uint4*)(g_xt + dst))[0] = make_uint4(hb[0], hb[1], hb[2], hb[3]);
    ((uint4*)(g_xt + dst))[1] = make_uint4(hb[4], hb[5], hb[6], hb[7]);
}

// ---------------- K1: conv3x3 via mma.sync (HMMA fp16, single pass) ----------------
// CTA: 96 co x 128 px, 192 threads (6 warps, each 32co x 64px), 2 CTAs/SM.
// 14 stages of 2 chunks (1 tap x 64 ci each); 2-stage ring (2 x 56 KB = 112 KB/CTA),
// ONE barrier per stage (half the barriers of the 27-stage version),
// mid-stage refill into the buffer freed by stage s-1 (safe after the barrier).
#define K1_CHUNK   28672                 // one chunk: W 12K + X 16K
#define K1_STG     (2 * K1_CHUNK)        // 57344
#define K1_NCHUNK  27
#define K1_NSTAGE  14                    // ceil(27/2)
#define K1_THREADS 192

__device__ __forceinline__ void k1_issue_chunk(
    int s, uint32_t dst, int tid, int co0, int P0, const __half* xt)
{
    const int tap = s / 3;
    const int kh  = tap / 3, kw = tap % 3;
    const int ci0 = (s % 3) * 64;

#pragma unroll
    for (int i = 0; i < 4; i++) {
        int idx = tid + i * K1_THREADS;
        int row = idx >> 3, seg = idx & 7;
        uint32_t off = SW128(row * 128 + seg * 16);
        size_t gsrc = (size_t)(co0 + row) * KTOT + tap * CIN + ci0 + seg * 8;
        cpa16(dst + off, g_wt + gsrc);
    }
#pragma unroll
    for (int i = 0; i < 6; i++) {
        int idx = tid + i * K1_THREADS;
        if (idx < 1024) {
            int row = idx >> 3, seg = idx & 7;
            uint32_t off = SW128(row * 128 + seg * 16);
            int p = P0 + row;
            int prow = (p >> 7) + kh;
            int pcol = (p & 127) + kw;
            size_t gsrc = ((size_t)prow * PAD + pcol) * CIN + ci0 + seg * 8;
            cpa16(dst + 12288 + off, xt + gsrc);
        }
    }
}

// issue both chunks of stage t into buffer; ONE commit
__device__ __forceinline__ void k1_issue_stage(
    int t, uint32_t dst, int tid, int co0, int P0, const __half* xt)
{
    k1_issue_chunk(2 * t, dst, tid, co0, P0, xt);
    if (2 * t + 1 < K1_NCHUNK)
        k1_issue_chunk(2 * t + 1, dst + K1_CHUNK, tid, co0, P0, xt);
    CP_COMMIT();
}

__global__ __launch_bounds__(K1_THREADS, 2) void k1_conv_mma() {
    extern __shared__ __align__(128) char dynraw[];
    const uint32_t dynbase = smem_to_u32(dynraw);

    const int tid  = threadIdx.x;
    const int wid  = tid >> 5;
    const int lane = tid & 31;

    const int P0  = blockIdx.x * 128;
    const int co0 = blockIdx.y * 96;
    const int n   = blockIdx.z;

    const __half* __restrict__ xt = g_xt + (size_t)n * PAD * PAD * CIN;

    const int cbase = (wid >> 1) * 32;
    const int n0    = (wid & 1) * 64;

    float c[2][8][4];
#pragma unroll
    for (int m = 0; m < 2; m++)
#pragma unroll
        for (int g = 0; g < 8; g++)
#pragma unroll
            for (int r = 0; r < 4; r++) c[m][g][r] = 0.f;

    const int a_rr   = (lane & 7) + ((lane & 8) ? 8 : 0);
    const int a_koff = (lane & 16) ? 16 : 0;
    const int b_rr   = (lane & 7) + ((lane & 16) ? 8 : 0);
    const int b_koff = (lane & 8) ? 16 : 0;

    // prologue: stage 0 into buffer 0
    k1_issue_stage(0, dynbase, tid, co0, P0, xt);

    for (int t = 0; t < K1_NSTAGE; t++) {
        CP_WAIT_0();                 // stage t resident (only group in flight)
        __syncthreads();             // all warps done with stage t-1

        const uint32_t stg = dynbase + (uint32_t)(t & 1) * K1_STG;
        const int nsub = (2 * t + 1 < K1_NCHUNK) ? 2 : 1;

        for (int cc = 0; cc < nsub; cc++) {
            const uint32_t Wh = stg + (uint32_t)cc * K1_CHUNK;
            const uint32_t Bx = Wh + 12288;

#pragma unroll
            for (int kk = 0; kk < 4; kk++) {
                uint32_t ah[2][4];
#pragma unroll
                for (int m = 0; m < 2; m++) {
                    uint32_t off = SW128((cbase + m * 16 + a_rr) * 128 + kk * 32 + a_koff);
                    LDSM_X4(ah[m], Wh + off);
                }
                uint32_t bx[4][4];
#pragma unroll
                for (int nb = 0; nb < 4; nb++) {
                    uint32_t off = SW128((n0 + nb * 16 + b_rr) * 128 + kk * 32 + b_koff);
                    LDSM_X4(bx[nb], Bx + off);
                }
#pragma unroll
                for (int m = 0; m < 2; m++) {
#pragma unroll
                    for (int nb = 0; nb < 4; nb++) {
                        MMAF16(c[m][nb * 2],     ah[m], bx[nb][0], bx[nb][1]);
                        MMAF16(c[m][nb * 2 + 1], ah[m], bx[nb][2], bx[nb][3]);
                    }
                }
            }

            // mid-stage refill after first sub-chunk: target buffer held stage t-1,
            // which every warp has finished (stage-t barrier above).
            if (cc == 0 && t + 1 < K1_NSTAGE) {
                k1_issue_stage(t + 1, dynbase + (uint32_t)((t + 1) & 1) * K1_STG,
                               tid, co0, P0, xt);
            }
        }
    }

    const int g  = lane >> 2;
    const int q  = lane & 3;

    if (co0 < 2 * CIN) {
#pragma unroll
        for (int m = 0; m < 2; m++) {
            int row0 = co0 + cbase + m * 16 + g;
#pragma unroll
            for (int ng = 0; ng < 8; ng++) {
                int col = P0 + n0 + ng * 8 + q * 2;
                __half2 h0 = __floats2half2_rn(c[m][ng][0], c[m][ng][1]);
                __half2 h1 = __floats2half2_rn(c[m][ng][2], c[m][ng][3]);
                *(__half2*)(g_c16 + ((size_t)(n * C3 + row0)) * HWP + col) = h0;
                *(__half2*)(g_c16 + ((size_t)(n * C3 + row0 + 8)) * HWP + col) = h1;
            }
        }
    } else {
        __half* st = (__half*)dynraw;
        __syncthreads();
#pragma unroll
        for (int m = 0; m < 2; m++) {
            int dloc = cbase + m * 16 + g;
#pragma unroll
            for (int ng = 0; ng < 8; ng++) {
                int col = n0 + ng * 8 + q * 2;
                st[ col      * 104 + dloc    ] = __float2half(c[m][ng][0]);
                st[(col + 1) * 104 + dloc    ] = __float2half(c[m][ng][1]);
                st[ col      * 104 + dloc + 8] = __float2half(c[m][ng][2]);
                st[(col + 1) * 104 + dloc + 8] = __float2half(c[m][ng][3]);
            }
        }
        __syncthreads();
        const int dbase = co0 - 2 * CIN;
#pragma unroll
        for (int i = 0; i < 8; i++) {
            int idx = tid + i * K1_THREADS;
            int px = idx / 12, chunk = idx % 12;
            uint4 v4 = *(uint4*)(st + px * 104 + chunk * 8);
            *(uint4*)(g_vt + ((size_t)n * HWP + P0 + px) * CIN + dbase + chunk * 8) = v4;
        }
    }
}

// ---------------- K2: S = q.k^T via HMMA; norms via fp32 sum-of-squares ----------------
#define K2_CHUNKS  16
#define K2_THREADS 128
#define K2_RED_OFF 98304
#define K2_SMEM    (98304 + (1024 + 64) * 4)

__global__ __launch_bounds__(K2_THREADS, 2) void k2_gram_mma() {
    extern __shared__ __align__(128) char dyn2[];
    const uint32_t dynbase = smem_to_u32(dyn2);
    float* red = (float*)(dyn2 + K2_RED_OFF);

    const int tid  = threadIdx.x;
    const int wid  = tid >> 5;
    const int lane = tid & 31;

    const int bx    = blockIdx.x;
    const int nh    = bx >> 4;
    const int chunk = bx & 15;
    const int n     = nh / HEADS;
    const int h     = nh % HEADS;

    const __half* qptr = g_c16 + ((size_t)(n * C3) + h * CH) * HWP;
    const __half* kptr = qptr + (size_t)CIN * HWP;
    const int p0 = chunk * 1024 + wid * 256;

    for (int i = tid; i < 1088; i += K2_THREADS) red[i] = 0.f;
    __syncthreads();

    const uint32_t wbase = dynbase + wid * 24576;

    const int a_rr   = (lane & 7) + ((lane & 8) ? 8 : 0);
    const int a_koff = (lane & 16) ? 16 : 0;
    const int b_rr   = (lane & 7) + ((lane & 16) ? 8 : 0);
    const int b_koff = (lane & 8) ? 16 : 0;

    float cS[2][4][4];
#pragma unroll
    for (int m = 0; m < 2; m++)
#pragma unroll
        for (int j = 0; j < 4; j++)
#pragma unroll
            for (int r = 0; r < 4; r++) cS[m][j][r] = 0.f;

    float qn_l = 0.f, kn_l = 0.f;

    auto stage = [&](int t, int b) {
        uint32_t qb = wbase + b * 8192;
        uint32_t kb = qb + 4096;
        int px = p0 + t * 64;
#pragma unroll
        for (int i = 0; i < 8; i++) {
            int idx = lane + i * 32;
            int row = idx >> 3, seg = idx & 7;
            uint32_t off = SW128(row * 128 + seg * 16);
            cpa16(qb + off, qptr + (size_t)row * HWP + px + seg * 8);
            cpa16(kb + off, kptr + (size_t)row * HWP + px + seg * 8);
        }
        CP_COMMIT();
    };

    stage(0, 0);
    stage(1, 1);

    for (int t = 0; t < 4; t++) {
        if (t + 2 < 4) stage(t + 2, (t + 2) % 3);
        else CP_COMMIT();
        CP_WAIT_2();
        __syncwarp();

        const uint32_t qb = wbase + (t % 3) * 8192;
        const uint32_t kb = qb + 4096;

#pragma unroll
        for (int kk = 0; kk < 4; kk++) {
            uint32_t aq[2][4], bk[2][4];
#pragma unroll
            for (int m = 0; m < 2; m++) {
                uint32_t offa = SW128((m * 16 + a_rr) * 128 + kk * 32 + a_koff);
                LDSM_X4(aq[m], qb + offa);
                uint32_t offb = SW128((m * 16 + b_rr) * 128 + kk * 32 + b_koff);
                LDSM_X4(bk[m], kb + offb);
            }
#pragma unroll
            for (int m = 0; m < 2; m++) {
#pragma unroll
                for (int nt = 0; nt < 2; nt++) {
                    MMAF16(cS[m][nt * 2],     aq[m], bk[nt][0], bk[nt][1]);
                    MMAF16(cS[m][nt * 2 + 1], aq[m], bk[nt][2], bk[nt][3]);
                }
            }
        }

        const char* qsm = dyn2 + (qb - dynbase);
        const char* ksm = dyn2 + (kb - dynbase);
#pragma unroll
        for (int seg = 0; seg < 8; seg++) {
            uint32_t off = SW128(lane * 128 + seg * 16);
            uint4 vq = *(const uint4*)(qsm + off);
            uint4 vk = *(const uint4*)(ksm + off);
            const __half2* hq = (const __half2*)&vq;
            const __half2* hk = (const __half2*)&vk;
#pragma unroll
            for (int j = 0; j < 4; j++) {
                float2 fq = __half22float2(hq[j]);
                float2 fk = __half22float2(hk[j]);
                qn_l += fq.x * fq.x + fq.y * fq.y;
                kn_l += fk.x * fk.x + fk.y * fk.y;
            }
        }
        __syncwarp();
    }

    const int g = lane >> 2;
    const int q4 = lane & 3;
#pragma unroll
    for (int m = 0; m < 2; m++) {
        int r0 = m * 16 + g;
#pragma unroll
        for (int j = 0; j < 4; j++) {
            int c0 = (j >> 1) * 16 + (j & 1) * 8 + q4 * 2;
            atomicAdd(&red[      r0 * 32 + c0],     cS[m][j][0]);
            atomicAdd(&red[      r0 * 32 + c0 + 1], cS[m][j][1]);
            atomicAdd(&red[(r0 + 8) * 32 + c0],     cS[m][j][2]);
            atomicAdd(&red[(r0 + 8) * 32 + c0 + 1], cS[m][j][3]);
        }
    }
    atomicAdd(&red[1024 + lane], qn_l);
    atomicAdd(&red[1056 + lane], kn_l);
    __syncthreads();

    for (int i = tid; i < 1024; i += K2_THREADS)
        atomicAdd(&g_S[nh * 1024 + i], red[i]);
    if (tid < 32) atomicAdd(&g_qn[nh * 32 + tid], red[1024 + tid]);
    else if (tid < 64) atomicAdd(&g_kn[nh * 32 + (tid - 32)], red[1056 + (tid - 32)]);
}

// ---------------- K34: softmax (redundant per slice) + proj slice, fp16 ----------------
#define K34_SLICES 24

__global__ __launch_bounds__(256) void k34_softmax_proj(
    const float* __restrict__ temperature, const float* __restrict__ pw)
{
    const int n     = blockIdx.x / K34_SLICES;
    const int slice = blockIdx.x % K34_SLICES;
    const int tid = threadIdx.x;

    __shared__ float at[HEADS * CH * CH];
    __shared__ float rk_s[HEADS * CH];

    if (tid < HEADS * CH)
        rk_s[tid] = 1.f / fmaxf(sqrtf(g_kn[n * HEADS * CH + tid]), EPS);
    __syncthreads();

    if (tid < HEADS * CH) {
        int h = tid >> 5, cidx = tid & 31;
        int nh = n * HEADS + h;
        float rq = 1.f / fmaxf(sqrtf(g_qn[nh * CH + cidx]), EPS);
        float t  = temperature[h];

        float row[CH];
        float m = -1e30f;
#pragma unroll
        for (int d = 0; d < CH; d++) {
            row[d] = g_S[nh * CH * CH + cidx * CH + d] * rq * rk_s[h * CH + d] * t;
            m = fmaxf(m, row[d]);
        }
        float sum = 0.f;
#pragma unroll
        for (int d = 0; d < CH; d++) { row[d] = expf(row[d] - m); sum += row[d]; }
        float inv = 1.f / sum;
#pragma unroll
        for (int d = 0; d < CH; d++)
            at[(h * CH + cidx) * CH + d] = row[d] * inv;
    }
    __syncthreads();

#pragma unroll
    for (int it = 0; it < 6; it++) {
        int idx = slice * 1536 + it * 256 + tid;
        int co = idx / CIN, dg = idx % CIN;
        int h = dg >> 5, d = dg & 31;
        float s = 0.f;
#pragma unroll
        for (int cc = 0; cc < CH; cc++)
            s += pw[co * CIN + h * CH + cc] * at[(h * CH + cc) * CH + d];
        g_mh[(size_t)n * CIN * CIN + idx] = __float2half(s);
    }
}

// ---------------- K5: out = M @ v + bias via HMMA fp16 ----------------
// CTA: 64 co x 128 px, 128 threads (4 warps, 2co x 2px), 2 CTAs/SM.
// grid (co, px, n): 3 co-tiles of the same px-tile run consecutively so v
// stays hot in L2 (removes the 2x v re-read from DRAM).
#define K5_STG     24576
#define K5_THREADS 128

__device__ __forceinline__ void k5_issue_chunk(
    int s, uint32_t dst, int tid, int co0, int P0, int n)
{
    const int d0 = s * 64;
#pragma unroll
    for (int i = 0; i < 4; i++) {
        int idx = tid + i * K5_THREADS;
        int row = idx >> 3, seg = idx & 7;
        uint32_t off = SW128(row * 128 + seg * 16);
        size_t gsrc = ((size_t)n * CIN + co0 + row) * CIN + d0 + seg * 8;
        cpa16(dst + off, g_mh + gsrc);
    }
#pragma unroll
    for (int i = 0; i < 8; i++) {
        int idx = tid + i * K5_THREADS;
        int row = idx >> 3, seg = idx & 7;
        uint32_t off = SW128(row * 128 + seg * 16);
        size_t gsrc = ((size_t)n * HWP + P0 + row) * CIN + d0 + seg * 8;
        cpa16(dst + 8192 + off, g_vt + gsrc);
    }
}

__global__ __launch_bounds__(K5_THREADS, 2) void k5_out_mma(
    const float* __restrict__ bias, float* __restrict__ out)
{
    extern __shared__ __align__(128) char dynraw[];
    const uint32_t dynbase = smem_to_u32(dynraw);

    const int tid  = threadIdx.x;
    const int wid  = tid >> 5;
    const int lane = tid & 31;

    const int co0 = blockIdx.x * 64;     // co fastest -> v reuse in L2
    const int P0  = blockIdx.y * 128;
    const int n   = blockIdx.z;

    const int cbase = (wid >> 1) * 32;
    const int n0    = (wid & 1) * 64;

    float c[2][8][4];
#pragma unroll
    for (int m = 0; m < 2; m++)
#pragma unroll
        for (int g = 0; g < 8; g++)
#pragma unroll
            for (int r = 0; r < 4; r++) c[m][g][r] = 0.f;

    const int a_rr   = (lane & 7) + ((lane & 8) ? 8 : 0);
    const int a_koff = (lane & 16) ? 16 : 0;
    const int b_rr   = (lane & 7) + ((lane & 16) ? 8 : 0);
    const int b_koff = (lane & 8) ? 16 : 0;

    k5_issue_chunk(0, dynbase,              tid, co0, P0, n); CP_COMMIT();
    k5_issue_chunk(1, dynbase + K5_STG,     tid, co0, P0, n); CP_COMMIT();
    k5_issue_chunk(2, dynbase + 2 * K5_STG, tid, co0, P0, n); CP_COMMIT();

#pragma unroll
    for (int s = 0; s < 3; s++) {
        if (s == 0)      { CP_WAIT_2(); }
        else if (s == 1) { CP_WAIT_1(); }
        else             { CP_WAIT_0(); }
        __syncthreads();

        const uint32_t Mh = dynbase + s * K5_STG;
        const uint32_t Bv = Mh + 8192;

#pragma unroll
        for (int kk = 0; kk < 4; kk++) {
            uint32_t ah[2][4];
#pragma unroll
            for (int m = 0; m < 2; m++) {
                uint32_t off = SW128((cbase + m * 16 + a_rr) * 128 + kk * 32 + a_koff);
                LDSM_X4(ah[m], Mh + off);
            }
            uint32_t bv[4][4];
#pragma unroll
            for (int nb = 0; nb < 4; nb++) {
                uint32_t off = SW128((n0 + nb * 16 + b_rr) * 128 + kk * 32 + b_koff);
                LDSM_X4(bv[nb], Bv + off);
            }
#pragma unroll
            for (int m = 0; m < 2; m++) {
#pragma unroll
                for (int nb = 0; nb < 4; nb++) {
                    MMAF16(c[m][nb * 2],     ah[m], bv[nb][0], bv[nb][1]);
                    MMAF16(c[m][nb * 2 + 1], ah[m], bv[nb][2], bv[nb][3]);
                }
            }
        }
    }

    const int g  = lane >> 2;
    const int q  = lane & 3;
#pragma unroll
    for (int m = 0; m < 2; m++) {
        int row0 = co0 + cbase + m * 16 + g;
        float b0 = bias[row0];
        float b1 = bias[row0 + 8];
#pragma unroll
        for (int ng = 0; ng < 8; ng++) {
            int col = P0 + n0 + ng * 8 + q * 2;
            float* o0 = out + ((size_t)(n * CIN + row0)) * HWP + col;
            float* o1 = o0 + (size_t)8 * HWP;
            o0[0] = c[m][ng][0] + b0; o0[1] = c[m][ng][1] + b0;
            o1[0] = c[m][ng][2] + b1; o1[1] = c[m][ng][3] + b1;
        }
    }
}

// ---------------- launcher ----------------
extern "C" void kernel_launch(void* const* d_in, const int* in_sizes, int n_in,
                              void* d_out, int out_size)
{
    const float* x    = (const float*)d_in[0];   // [8,192,128,128]
    const float* qkvw = (const float*)d_in[1];   // [576,192,3,3]
    const float* pw   = (const float*)d_in[2];   // [192,192,1,1]
    const float* pb   = (const float*)d_in[3];   // [192]
    const float* temp = (const float*)d_in[4];   // [6]
    float* out = (float*)d_out;

    cudaFuncSetAttribute(k1_conv_mma,  cudaFuncAttributeMaxDynamicSharedMemorySize, 2 * K1_STG);
    cudaFuncSetAttribute(k2_gram_mma,  cudaFuncAttributeMaxDynamicSharedMemorySize, K2_SMEM);
    cudaFuncSetAttribute(k5_out_mma,   cudaFuncAttributeMaxDynamicSharedMemorySize, 3 * K5_STG);

    // launches: 1 fused setup+transpose, 2 k1, 3 k2, 4 k34 (profiled), 5 k5
    k0t_setup_transpose<<<KT_BLOCKS + SETUP_BLOCKS, 256>>>(qkvw, x);  // 1

    {
        dim3 g1(HWP / 128, C3 / 96, NB);   // 128 x 6 x 8
        k1_conv_mma<<<g1, K1_THREADS, 2 * K1_STG>>>();                // 2
    }

    k2_gram_mma<<<NH * K2_CHUNKS, K2_THREADS, K2_SMEM>>>();           // 3

    k34_softmax_proj<<<NB * K34_SLICES, 256>>>(temp, pw);             // 4 (profiled)

    {
        dim3 g5(CIN / 64, HWP / 128, NB);  // 3 x 128 x 8 (co fastest)
        k5_out_mma<<<g5, K5_THREADS, 3 * K5_STG>>>(pb, out);          // 5
    }
}